// round 1
// baseline (speedup 1.0000x reference)
#include <cuda_runtime.h>
#include <math.h>

// ARIMA sliding-window loss, algebraically collapsed:
//   err[t] = y[t+33] - K1*FIR(g, win) + (K1*w0 - 1)*mean - K2*std
//   loss   = (sum(y[:33]^2) + sum(err^2)) / S
// g[] is a precomputed 32-tap FIR from ar_weight; K1/K2 fold rev_weight/rev_bias/ar_bias.

#define PW    32
#define T0    33
#define EPSF  1e-5f
#define TPB   256
#define ITEMS 4
#define TILE  (TPB * ITEMS)     // 1024 t-values per block
#define MAXBLOCKS 8192

__device__ double g_partials[MAXBLOCKS];

__global__ void __launch_bounds__(TPB) arima_main(
    const float* __restrict__ y,
    const float* __restrict__ w,
    const float* __restrict__ ab,
    const float* __restrict__ rw_,
    const float* __restrict__ rb_,
    int T, int S)
{
    __shared__ float  sy[TILE + PW + 1];
    __shared__ float  sg[PW];
    __shared__ float  sc[3];
    __shared__ double sred[TPB];

    const int tid = threadIdx.x;
    const int tb  = blockIdx.x * TILE;

    // FIR coefficients (derived from ar_weight + the differencing/pred_d structure)
    if (tid < PW) {
        float wj  = w[tid];
        float wj1 = (tid < PW - 1) ? w[tid + 1] : 0.0f;
        float gv  = wj - wj1;
        if (tid == PW - 2) gv -= 1.0f;   // g[30] = w30 - w31 - 1
        if (tid == PW - 1) gv += 1.0f;   // g[31] = w31 + 1
        sg[tid] = gv;
    }
    if (tid == 0) {
        float rw = rw_[0], rb = rb_[0], b = ab[0], w0 = w[0];
        float denom = rw + EPSF * EPSF;          // matches fp32 reference exactly
        float K1 = rw / denom;
        float K2 = (w0 * rb - rb + b) / denom;
        sc[0] = K1;
        sc[1] = K2;
        sc[2] = fmaf(K1, w0, -1.0f);             // M1 = K1*w0 - 1
    }

    // Stage the tile: y[tb+1 .. tb+TILE+32]
    for (int i = tid; i < TILE + PW; i += TPB) {
        int gi = tb + 1 + i;
        sy[i] = (gi < S) ? y[gi] : 0.0f;
    }
    __syncthreads();

    const float K1 = sc[0], K2 = sc[1], M1 = sc[2];
    double esum = 0.0;

    #pragma unroll
    for (int k = 0; k < ITEMS; k++) {
        int l = tid + k * TPB;
        int t = tb + l;
        if (t < T) {
            float sum = 0.f, sq = 0.f, fir = 0.f;
            #pragma unroll
            for (int j = 0; j < PW; j++) {
                float x = sy[l + j];
                sum += x;
                sq  = fmaf(x, x, sq);
                fir = fmaf(sg[j], x, fir);
            }
            float mean = sum * (1.0f / PW);
            float var  = fmaf(-mean, mean, sq * (1.0f / PW));
            float sd   = sqrtf(var + EPSF);
            float yt   = sy[l + PW];
            float err  = fmaf(-K1, fir, yt) + fmaf(M1, mean, -K2 * sd);
            esum += (double)err * (double)err;
        }
    }

    sred[tid] = esum;
    __syncthreads();
    #pragma unroll
    for (int s = TPB / 2; s > 0; s >>= 1) {
        if (tid < s) sred[tid] += sred[tid + s];
        __syncthreads();
    }
    if (tid == 0) g_partials[blockIdx.x] = sred[0];
}

__global__ void __launch_bounds__(256) arima_reduce(
    const float* __restrict__ y, float* __restrict__ out, int nblocks, int S)
{
    __shared__ double sred[256];
    const int tid = threadIdx.x;
    double s = 0.0;
    for (int i = tid; i < nblocks; i += 256) s += g_partials[i];
    for (int i = tid; i < T0; i += 256) { double v = (double)y[i]; s += v * v; }
    sred[tid] = s;
    __syncthreads();
    #pragma unroll
    for (int k = 128; k > 0; k >>= 1) {
        if (tid < k) sred[tid] += sred[tid + k];
        __syncthreads();
    }
    if (tid == 0) out[0] = (float)(sred[0] / (double)S);
}

extern "C" void kernel_launch(void* const* d_in, const int* in_sizes, int n_in,
                              void* d_out, int out_size)
{
    const float* y  = (const float*)d_in[0];
    const float* w  = (const float*)d_in[1];
    const float* ab = (const float*)d_in[2];
    const float* rw = (const float*)d_in[3];
    const float* rb = (const float*)d_in[4];
    int S = in_sizes[0];
    int T = S - T0;
    int nblocks = (T + TILE - 1) / TILE;
    if (nblocks > MAXBLOCKS) nblocks = MAXBLOCKS;  // S=1M -> 1024 blocks; guard only
    arima_main<<<nblocks, TPB>>>(y, w, ab, rw, rb, T, S);
    arima_reduce<<<1, 256>>>(y, (float*)d_out, nblocks, S);
}